// round 1
// baseline (speedup 1.0000x reference)
#include <cuda_runtime.h>
#include <cuda_bf16.h>
#include <math.h>

#define BB 16
#define DD 4
#define HH 288
#define WW 800
#define NN (HH * WW)     // 230400
#define LL 5
#define DELTA_V 0.5f

// Scratch accumulators (allocation-free: __device__ globals)
__device__ float g_sums[BB][LL][DD];
__device__ float g_cnts[BB][LL];
__device__ float g_hinge[BB][LL];
__device__ float g_ce[2];   // [0]=sum(w*nll), [1]=sum(w)

__global__ void k_zero() {
    int t = threadIdx.x;
    float* ps = &g_sums[0][0][0];
    for (int i = t; i < BB * LL * DD; i += blockDim.x) ps[i] = 0.f;
    float* pc = &g_cnts[0][0];
    float* ph = &g_hinge[0][0];
    for (int i = t; i < BB * LL; i += blockDim.x) { pc[i] = 0.f; ph[i] = 0.f; }
    if (t < 2) g_ce[t] = 0.f;
}

__device__ __forceinline__ float warp_red(float v) {
    #pragma unroll
    for (int o = 16; o > 0; o >>= 1) v += __shfl_down_sync(0xffffffffu, v, o);
    return v;
}

// Pass 1: per-(batch,label) embedding sums + counts, and weighted CE partials.
__global__ void k_accum(const float* __restrict__ emb,
                        const float* __restrict__ bin,
                        const int*   __restrict__ seg) {
    const int b = blockIdx.y;
    const float* ep = emb + (size_t)b * DD * NN;
    const float* bp = bin + (size_t)b * 2 * NN;
    const int*   sp = seg + (size_t)b * NN;

    float s[LL][DD];
    float c[LL];
    #pragma unroll
    for (int l = 0; l < LL; l++) {
        c[l] = 0.f;
        #pragma unroll
        for (int d = 0; d < DD; d++) s[l][d] = 0.f;
    }
    float ce_num = 0.f, ce_den = 0.f;

    for (int n = blockIdx.x * blockDim.x + threadIdx.x; n < NN;
         n += gridDim.x * blockDim.x) {
        int lab = sp[n];
        float e0 = ep[n];
        float e1 = ep[NN + n];
        float e2 = ep[2 * NN + n];
        float e3 = ep[3 * NN + n];
        #pragma unroll
        for (int l = 0; l < LL; l++) {
            float m = (lab == l) ? 1.f : 0.f;
            c[l]    += m;
            s[l][0] = fmaf(m, e0, s[l][0]);
            s[l][1] = fmaf(m, e1, s[l][1]);
            s[l][2] = fmaf(m, e2, s[l][2]);
            s[l][3] = fmaf(m, e3, s[l][3]);
        }
        // weighted binary cross entropy (2-class log-softmax)
        float x0 = bp[n];
        float x1 = bp[NN + n];
        float mx = fmaxf(x0, x1);
        float lse = mx + logf(expf(x0 - mx) + expf(x1 - mx));
        float xt = (lab > 0) ? x1 : x0;
        float nll = lse - xt;
        float w = (lab > 0) ? 1.f : 0.5f;
        ce_num = fmaf(w, nll, ce_num);
        ce_den += w;
    }

    __shared__ float sh[LL * DD + LL + 2];
    if (threadIdx.x < LL * DD + LL + 2) sh[threadIdx.x] = 0.f;
    __syncthreads();

    const int lane = threadIdx.x & 31;
    #pragma unroll
    for (int l = 0; l < LL; l++) {
        #pragma unroll
        for (int d = 0; d < DD; d++) {
            float v = warp_red(s[l][d]);
            if (lane == 0) atomicAdd(&sh[l * DD + d], v);
        }
        float v = warp_red(c[l]);
        if (lane == 0) atomicAdd(&sh[LL * DD + l], v);
    }
    {
        float v = warp_red(ce_num);
        if (lane == 0) atomicAdd(&sh[LL * DD + LL], v);
        v = warp_red(ce_den);
        if (lane == 0) atomicAdd(&sh[LL * DD + LL + 1], v);
    }
    __syncthreads();

    if (threadIdx.x < LL * DD) {
        atomicAdd(&g_sums[b][threadIdx.x / DD][threadIdx.x % DD], sh[threadIdx.x]);
    } else if (threadIdx.x < LL * DD + LL) {
        atomicAdd(&g_cnts[b][threadIdx.x - LL * DD], sh[threadIdx.x]);
    } else if (threadIdx.x < LL * DD + LL + 2) {
        atomicAdd(&g_ce[threadIdx.x - LL * DD - LL], sh[threadIdx.x]);
    }
}

// Pass 2: per-pixel hinge distance to own-label centroid, summed per (b,label).
__global__ void k_hinge(const float* __restrict__ emb,
                        const int*   __restrict__ seg) {
    const int b = blockIdx.y;
    __shared__ float mean[LL][DD];
    if (threadIdx.x < LL * DD) {
        int l = threadIdx.x / DD, d = threadIdx.x % DD;
        mean[l][d] = g_sums[b][l][d] / fmaxf(g_cnts[b][l], 1.f);
    }
    __syncthreads();

    const float* ep = emb + (size_t)b * DD * NN;
    const int*   sp = seg + (size_t)b * NN;

    float hacc[LL];
    #pragma unroll
    for (int l = 0; l < LL; l++) hacc[l] = 0.f;

    for (int n = blockIdx.x * blockDim.x + threadIdx.x; n < NN;
         n += gridDim.x * blockDim.x) {
        int lab = sp[n];
        float d0 = ep[n]          - mean[lab][0];
        float d1 = ep[NN + n]     - mean[lab][1];
        float d2 = ep[2 * NN + n] - mean[lab][2];
        float d3 = ep[3 * NN + n] - mean[lab][3];
        float sq = fmaf(d0, d0, fmaf(d1, d1, fmaf(d2, d2, d3 * d3)));
        float dist = sqrtf(sq);
        float h = fmaxf(dist - DELTA_V, 0.f);
        float hs = h * h;
        #pragma unroll
        for (int l = 0; l < LL; l++)
            hacc[l] += (lab == l) ? hs : 0.f;
    }

    __shared__ float sh[LL];
    if (threadIdx.x < LL) sh[threadIdx.x] = 0.f;
    __syncthreads();
    const int lane = threadIdx.x & 31;
    #pragma unroll
    for (int l = 0; l < LL; l++) {
        float v = warp_red(hacc[l]);
        if (lane == 0) atomicAdd(&sh[l], v);
    }
    __syncthreads();
    if (threadIdx.x < LL) atomicAdd(&g_hinge[b][threadIdx.x], sh[threadIdx.x]);
}

__global__ void k_final(float* __restrict__ out) {
    if (threadIdx.x == 0 && blockIdx.x == 0) {
        float seg_loss = g_ce[0] / g_ce[1];
        float tot = 0.f;
        for (int b = 0; b < BB; b++) {
            int nl = 0;
            float acc = 0.f;
            for (int l = 1; l < LL; l++) {
                float cc = g_cnts[b][l];
                if (cc > 0.f) {
                    nl++;
                    acc += g_hinge[b][l] / fmaxf(cc, 1.f);
                }
            }
            tot += (nl > 0) ? acc / (float)nl : 0.f;
        }
        float var_loss = tot / (float)BB;
        // dist_loss == 0 exactly (reference adds DELTA_D to all pairwise
        // distances before relu(DELTA_D - cd)); reg_loss == 0.
        out[0] = seg_loss + var_loss;
    }
}

extern "C" void kernel_launch(void* const* d_in, const int* in_sizes, int n_in,
                              void* d_out, int out_size) {
    const float* emb = (const float*)d_in[0];  // [16,4,288,800] f32
    const float* bin = (const float*)d_in[1];  // [16,2,288,800] f32
    const int*   seg = (const int*)d_in[2];    // [16,288,800] i32
    float* out = (float*)d_out;

    k_zero<<<1, 256>>>();
    dim3 grid(148, BB);
    k_accum<<<grid, 256>>>(emb, bin, seg);
    k_hinge<<<grid, 256>>>(emb, seg);
    k_final<<<1, 32>>>(out);
}

// round 2
// speedup vs baseline: 1.5506x; 1.5506x over previous
#include <cuda_runtime.h>
#include <math.h>

#define BB 16
#define DD 4
#define HH 288
#define WW 800
#define NN (HH * WW)        // 230400
#define NQ (NN / 4)         // 57600 quads
#define LL 5
#define DELTA_V 0.5f
#define GX 75
#define TPB 256
// GX*TPB = 19200 ; NQ / 19200 = 3 exact iterations, no bounds checks

// Scratch (allocation-free __device__ globals)
__device__ float g_sums[BB][LL][DD];
__device__ float g_cnts[BB][LL];
__device__ float g_ce;          // sum(w * nll)
__device__ float g_var;         // accumulated var_loss (already normalized)
__device__ unsigned int g_done; // pass-2 completion counter

__global__ void k_zero() {
    int t = threadIdx.x;
    float* ps = &g_sums[0][0][0];
    for (int i = t; i < BB * LL * DD; i += blockDim.x) ps[i] = 0.f;
    float* pc = &g_cnts[0][0];
    for (int i = t; i < BB * LL; i += blockDim.x) pc[i] = 0.f;
    if (t == 0) { g_ce = 0.f; g_var = 0.f; g_done = 0u; }
}

__device__ __forceinline__ float warp_red(float v) {
    #pragma unroll
    for (int o = 16; o > 0; o >>= 1) v += __shfl_down_sync(0xffffffffu, v, o);
    return v;
}

__device__ __forceinline__ void px1(int lab,
                                    float a0, float a1, float a2, float a3,
                                    float x0, float x1,
                                    unsigned long long* s01,
                                    unsigned long long* s23,
                                    float* cnt, float& ce) {
    unsigned long long e01, e23;
    asm("mov.b64 %0, {%1, %2};" : "=l"(e01) : "f"(a0), "f"(a1));
    asm("mov.b64 %0, {%1, %2};" : "=l"(e23) : "f"(a2), "f"(a3));
    #pragma unroll
    for (int l = 0; l < LL; l++) {
        // hand-predicated: setp + 3 @p ops, no SEL/branches
        asm volatile("{\n\t"
            ".reg .pred p;\n\t"
            "setp.eq.s32 p, %3, %4;\n\t"
            "@p add.f32 %0, %0, 0f3F800000;\n\t"
            "@p add.rn.f32x2 %1, %1, %5;\n\t"
            "@p add.rn.f32x2 %2, %2, %6;\n\t"
            "}"
            : "+f"(cnt[l]), "+l"(s01[l]), "+l"(s23[l])
            : "r"(lab), "r"(l), "l"(e01), "l"(e23));
    }
    // weighted binary CE via softplus: nll = max(u,0) + log(1+exp(-|u|))
    float z = x1 - x0;
    bool fg = lab > 0;
    float u = fg ? -z : z;
    float eu = __expf(-fabsf(u));
    float sp = fmaxf(u, 0.f) + __logf(1.f + eu);
    ce += fg ? sp : 0.5f * sp;
}

// Pass 1: per-(batch,label) embedding sums + counts + CE numerator.
__global__ void __launch_bounds__(TPB) k_pass1(const float* __restrict__ emb,
                                               const float* __restrict__ bin,
                                               const int*   __restrict__ seg) {
    const int b = blockIdx.y;
    const float4* ep = (const float4*)(emb + (size_t)b * DD * NN);
    const float4* bp = (const float4*)(bin + (size_t)b * 2 * NN);
    const int4*   sp = (const int4*)(seg + (size_t)b * NN);

    unsigned long long s01[LL], s23[LL];
    float cnt[LL];
    #pragma unroll
    for (int l = 0; l < LL; l++) { s01[l] = 0ull; s23[l] = 0ull; cnt[l] = 0.f; }
    float ce = 0.f;

    #pragma unroll
    for (int it = 0; it < 3; it++) {
        int q = it * (GX * TPB) + blockIdx.x * TPB + threadIdx.x;
        float4 e0 = ep[q];
        float4 e1 = ep[q + NQ];
        float4 e2 = ep[q + 2 * NQ];
        float4 e3 = ep[q + 3 * NQ];
        float4 c0 = bp[q];
        float4 c1 = bp[q + NQ];
        int4   lv = sp[q];
        px1(lv.x, e0.x, e1.x, e2.x, e3.x, c0.x, c1.x, s01, s23, cnt, ce);
        px1(lv.y, e0.y, e1.y, e2.y, e3.y, c0.y, c1.y, s01, s23, cnt, ce);
        px1(lv.z, e0.z, e1.z, e2.z, e3.z, c0.z, c1.z, s01, s23, cnt, ce);
        px1(lv.w, e0.w, e1.w, e2.w, e3.w, c0.w, c1.w, s01, s23, cnt, ce);
    }

    // unpack to 26 scalars: 20 sums, 5 counts, 1 ce
    float vals[26];
    #pragma unroll
    for (int l = 0; l < LL; l++) {
        float lo, hi;
        asm("mov.b64 {%0, %1}, %2;" : "=f"(lo), "=f"(hi) : "l"(s01[l]));
        vals[l * 4 + 0] = lo; vals[l * 4 + 1] = hi;
        asm("mov.b64 {%0, %1}, %2;" : "=f"(lo), "=f"(hi) : "l"(s23[l]));
        vals[l * 4 + 2] = lo; vals[l * 4 + 3] = hi;
        vals[20 + l] = cnt[l];
    }
    vals[25] = ce;

    __shared__ float sh[26];
    if (threadIdx.x < 26) sh[threadIdx.x] = 0.f;
    __syncthreads();
    const int lane = threadIdx.x & 31;
    #pragma unroll
    for (int i = 0; i < 26; i++) {
        float v = warp_red(vals[i]);
        if (lane == 0) atomicAdd(&sh[i], v);
    }
    __syncthreads();
    if (threadIdx.x < 20) {
        atomicAdd(&g_sums[b][threadIdx.x >> 2][threadIdx.x & 3], sh[threadIdx.x]);
    } else if (threadIdx.x < 25) {
        atomicAdd(&g_cnts[b][threadIdx.x - 20], sh[threadIdx.x]);
    } else if (threadIdx.x == 25) {
        atomicAdd(&g_ce, sh[25]);
    }
}

// Pass 2: per-pixel hinge, pre-normalized weight LUT, fused finalization.
__global__ void __launch_bounds__(TPB) k_pass2(const float* __restrict__ emb,
                                               const int*   __restrict__ seg,
                                               float* __restrict__ out) {
    const int b = blockIdx.y;
    __shared__ float m0[LL], m1[LL], m2[LL], m3[LL], wsh[LL];
    __shared__ bool sh_last;
    if (threadIdx.x < LL) {
        int l = threadIdx.x;
        float c = g_cnts[b][l];
        float inv = 1.f / fmaxf(c, 1.f);
        m0[l] = g_sums[b][l][0] * inv;
        m1[l] = g_sums[b][l][1] * inv;
        m2[l] = g_sums[b][l][2] * inv;
        m3[l] = g_sums[b][l][3] * inv;
        int nl = 0;
        #pragma unroll
        for (int j = 1; j < LL; j++) nl += (g_cnts[b][j] > 0.f) ? 1 : 0;
        float w = 0.f;
        if (l > 0 && c > 0.f && nl > 0)
            w = 1.f / (c * (float)nl * (float)BB);
        wsh[l] = w;
    }
    __syncthreads();

    const float4* ep = (const float4*)(emb + (size_t)b * DD * NN);
    const int4*   sp = (const int4*)(seg + (size_t)b * NN);

    float acc = 0.f;
    #pragma unroll
    for (int it = 0; it < 3; it++) {
        int q = it * (GX * TPB) + blockIdx.x * TPB + threadIdx.x;
        float4 e0 = ep[q];
        float4 e1 = ep[q + NQ];
        float4 e2 = ep[q + 2 * NQ];
        float4 e3 = ep[q + 3 * NQ];
        int4 lv = sp[q];
        #pragma unroll
        for (int j = 0; j < 4; j++) {
            int lab = (j == 0) ? lv.x : (j == 1) ? lv.y : (j == 2) ? lv.z : lv.w;
            float a0 = (j == 0) ? e0.x : (j == 1) ? e0.y : (j == 2) ? e0.z : e0.w;
            float a1 = (j == 0) ? e1.x : (j == 1) ? e1.y : (j == 2) ? e1.z : e1.w;
            float a2 = (j == 0) ? e2.x : (j == 1) ? e2.y : (j == 2) ? e2.z : e2.w;
            float a3 = (j == 0) ? e3.x : (j == 1) ? e3.y : (j == 2) ? e3.z : e3.w;
            float d0 = a0 - m0[lab];
            float d1 = a1 - m1[lab];
            float d2 = a2 - m2[lab];
            float d3 = a3 - m3[lab];
            float sq = fmaf(d0, d0, fmaf(d1, d1, fmaf(d2, d2, d3 * d3)));
            float dist = sqrtf(sq);
            float h = fmaxf(dist - DELTA_V, 0.f);
            acc = fmaf(wsh[lab], h * h, acc);
        }
    }

    __shared__ float shv[8];
    const int lane = threadIdx.x & 31;
    const int wid = threadIdx.x >> 5;
    float v = warp_red(acc);
    if (lane == 0) shv[wid] = v;
    __syncthreads();
    if (threadIdx.x == 0) {
        float bsum = 0.f;
        #pragma unroll
        for (int i = 0; i < 8; i++) bsum += shv[i];
        atomicAdd(&g_var, bsum);
        __threadfence();
        unsigned int old = atomicAdd(&g_done, 1u);
        sh_last = (old == (unsigned)(GX * BB - 1));
    }
    __syncthreads();
    if (sh_last && threadIdx.x == 0) {
        __threadfence();
        float bg = 0.f;
        #pragma unroll
        for (int bb = 0; bb < BB; bb++) bg += *((volatile float*)&g_cnts[bb][0]);
        float den = (float)BB * (float)NN - 0.5f * bg;
        float seg_loss = (*((volatile float*)&g_ce)) / den;
        float var_loss = *((volatile float*)&g_var);
        // dist_loss == 0 exactly (reference adds DELTA_D before the relu),
        // reg_loss == 0.
        out[0] = seg_loss + var_loss;
    }
}

extern "C" void kernel_launch(void* const* d_in, const int* in_sizes, int n_in,
                              void* d_out, int out_size) {
    const float* emb = (const float*)d_in[0];  // [16,4,288,800] f32
    const float* bin = (const float*)d_in[1];  // [16,2,288,800] f32
    const int*   seg = (const int*)d_in[2];    // [16,288,800] i32
    float* out = (float*)d_out;

    k_zero<<<1, 256>>>();
    dim3 grid(GX, BB);
    k_pass1<<<grid, TPB>>>(emb, bin, seg);
    k_pass2<<<grid, TPB>>>(emb, seg, out);
}

// round 5
// speedup vs baseline: 1.8012x; 1.1616x over previous
#include <cuda_runtime.h>
#include <math.h>

#define BB 16
#define DD 4
#define HH 288
#define WW 800
#define NN (HH * WW)        // 230400
#define NQ (NN / 4)         // 57600 quads
#define LL 5
#define DELTA_V 0.5f
#define GX 25
#define TPB 256
#define ITERS 9
// GX*TPB*ITERS = 25*256*9 = 57600 = NQ exactly; no bounds checks.
// 400 total blocks -> single wave on 148 SMs at any occupancy >= 3.

// Scratch (allocation-free __device__ globals; explicitly zero-initialized at
// module load, and re-zeroed by the last pass-2 block after each run => every
// graph replay starts clean without a dedicated zeroing kernel).
__device__ float g_sums[BB][LL][DD] = {};
__device__ float g_cnts[BB][LL] = {};
__device__ float g_ce = 0.f;          // sum(w * nll)
__device__ float g_var = 0.f;         // accumulated var_loss (pre-normalized)
__device__ unsigned int g_done = 0u;  // pass-2 completion counter

__device__ __forceinline__ float warp_red(float v) {
    #pragma unroll
    for (int o = 16; o > 0; o >>= 1) v += __shfl_down_sync(0xffffffffu, v, o);
    return v;
}

__device__ __forceinline__ void px1(int lab,
                                    float a0, float a1, float a2, float a3,
                                    float x0, float x1,
                                    unsigned long long* s01,
                                    unsigned long long* s23,
                                    float* cnt, float& ce) {
    unsigned long long e01, e23;
    asm("mov.b64 %0, {%1, %2};" : "=l"(e01) : "f"(a0), "f"(a1));
    asm("mov.b64 %0, {%1, %2};" : "=l"(e23) : "f"(a2), "f"(a3));
    #pragma unroll
    for (int l = 0; l < LL; l++) {
        // hand-predicated: setp + 3 @p ops, no SEL/branches
        asm volatile("{\n\t"
            ".reg .pred p;\n\t"
            "setp.eq.s32 p, %3, %4;\n\t"
            "@p add.f32 %0, %0, 0f3F800000;\n\t"
            "@p add.rn.f32x2 %1, %1, %5;\n\t"
            "@p add.rn.f32x2 %2, %2, %6;\n\t"
            "}"
            : "+f"(cnt[l]), "+l"(s01[l]), "+l"(s23[l])
            : "r"(lab), "r"(l), "l"(e01), "l"(e23));
    }
    // weighted binary CE via softplus: nll = max(u,0) + log(1+exp(-|u|))
    float z = x1 - x0;
    bool fg = lab > 0;
    float u = fg ? -z : z;
    float eu = __expf(-fabsf(u));
    float sp = fmaxf(u, 0.f) + __logf(1.f + eu);
    ce += fg ? sp : 0.5f * sp;
}

// Pass 1: per-(batch,label) embedding sums + counts + CE numerator.
__global__ void __launch_bounds__(TPB) k_pass1(const float* __restrict__ emb,
                                               const float* __restrict__ bin,
                                               const int*   __restrict__ seg) {
    const int b = blockIdx.y;
    const float4* ep = (const float4*)(emb + (size_t)b * DD * NN);
    const float4* bp = (const float4*)(bin + (size_t)b * 2 * NN);
    const int4*   sp = (const int4*)(seg + (size_t)b * NN);

    unsigned long long s01[LL], s23[LL];
    float cnt[LL];
    #pragma unroll
    for (int l = 0; l < LL; l++) { s01[l] = 0ull; s23[l] = 0ull; cnt[l] = 0.f; }
    float ce = 0.f;

    #pragma unroll 3
    for (int it = 0; it < ITERS; it++) {
        int q = it * (GX * TPB) + blockIdx.x * TPB + threadIdx.x;
        float4 e0 = ep[q];
        float4 e1 = ep[q + NQ];
        float4 e2 = ep[q + 2 * NQ];
        float4 e3 = ep[q + 3 * NQ];
        float4 c0 = bp[q];
        float4 c1 = bp[q + NQ];
        int4   lv = sp[q];
        px1(lv.x, e0.x, e1.x, e2.x, e3.x, c0.x, c1.x, s01, s23, cnt, ce);
        px1(lv.y, e0.y, e1.y, e2.y, e3.y, c0.y, c1.y, s01, s23, cnt, ce);
        px1(lv.z, e0.z, e1.z, e2.z, e3.z, c0.z, c1.z, s01, s23, cnt, ce);
        px1(lv.w, e0.w, e1.w, e2.w, e3.w, c0.w, c1.w, s01, s23, cnt, ce);
    }

    // unpack to 26 scalars: 20 sums, 5 counts, 1 ce
    float vals[26];
    #pragma unroll
    for (int l = 0; l < LL; l++) {
        float lo, hi;
        asm("mov.b64 {%0, %1}, %2;" : "=f"(lo), "=f"(hi) : "l"(s01[l]));
        vals[l * 4 + 0] = lo; vals[l * 4 + 1] = hi;
        asm("mov.b64 {%0, %1}, %2;" : "=f"(lo), "=f"(hi) : "l"(s23[l]));
        vals[l * 4 + 2] = lo; vals[l * 4 + 3] = hi;
        vals[20 + l] = cnt[l];
    }
    vals[25] = ce;

    __shared__ float sh[26];
    if (threadIdx.x < 26) sh[threadIdx.x] = 0.f;
    __syncthreads();
    const int lane = threadIdx.x & 31;
    #pragma unroll
    for (int i = 0; i < 26; i++) {
        float v = warp_red(vals[i]);
        if (lane == 0) atomicAdd(&sh[i], v);
    }
    __syncthreads();
    if (threadIdx.x < 20) {
        atomicAdd(&g_sums[b][threadIdx.x >> 2][threadIdx.x & 3], sh[threadIdx.x]);
    } else if (threadIdx.x < 25) {
        atomicAdd(&g_cnts[b][threadIdx.x - 20], sh[threadIdx.x]);
    } else if (threadIdx.x == 25) {
        atomicAdd(&g_ce, sh[25]);
    }
}

// Pass 2: per-pixel hinge with pre-normalized weight LUT, fused finalization
// and scratch cleanup for the next graph replay.
__global__ void __launch_bounds__(TPB) k_pass2(const float* __restrict__ emb,
                                               const int*   __restrict__ seg,
                                               float* __restrict__ out) {
    const int b = blockIdx.y;
    __shared__ float m0[LL], m1[LL], m2[LL], m3[LL], wsh[LL];
    __shared__ bool sh_last;
    if (threadIdx.x < LL) {
        int l = threadIdx.x;
        float c = g_cnts[b][l];
        float inv = 1.f / fmaxf(c, 1.f);
        m0[l] = g_sums[b][l][0] * inv;
        m1[l] = g_sums[b][l][1] * inv;
        m2[l] = g_sums[b][l][2] * inv;
        m3[l] = g_sums[b][l][3] * inv;
        int nl = 0;
        #pragma unroll
        for (int j = 1; j < LL; j++) nl += (g_cnts[b][j] > 0.f) ? 1 : 0;
        float w = 0.f;
        if (l > 0 && c > 0.f && nl > 0)
            w = 1.f / (c * (float)nl * (float)BB);
        wsh[l] = w;
    }
    __syncthreads();

    const float4* ep = (const float4*)(emb + (size_t)b * DD * NN);
    const int4*   sp = (const int4*)(seg + (size_t)b * NN);

    float acc = 0.f;
    #pragma unroll 3
    for (int it = 0; it < ITERS; it++) {
        int q = it * (GX * TPB) + blockIdx.x * TPB + threadIdx.x;
        float4 e0 = ep[q];
        float4 e1 = ep[q + NQ];
        float4 e2 = ep[q + 2 * NQ];
        float4 e3 = ep[q + 3 * NQ];
        int4 lv = sp[q];
        #pragma unroll
        for (int j = 0; j < 4; j++) {
            int lab = (j == 0) ? lv.x : (j == 1) ? lv.y : (j == 2) ? lv.z : lv.w;
            float a0 = (j == 0) ? e0.x : (j == 1) ? e0.y : (j == 2) ? e0.z : e0.w;
            float a1 = (j == 0) ? e1.x : (j == 1) ? e1.y : (j == 2) ? e1.z : e1.w;
            float a2 = (j == 0) ? e2.x : (j == 1) ? e2.y : (j == 2) ? e2.z : e2.w;
            float a3 = (j == 0) ? e3.x : (j == 1) ? e3.y : (j == 2) ? e3.z : e3.w;
            float d0 = a0 - m0[lab];
            float d1 = a1 - m1[lab];
            float d2 = a2 - m2[lab];
            float d3 = a3 - m3[lab];
            float sq = fmaf(d0, d0, fmaf(d1, d1, fmaf(d2, d2, d3 * d3)));
            float dist = sqrtf(sq);
            float h = fmaxf(dist - DELTA_V, 0.f);
            acc = fmaf(wsh[lab], h * h, acc);
        }
    }

    __shared__ float shv[8];
    const int lane = threadIdx.x & 31;
    const int wid = threadIdx.x >> 5;
    float v = warp_red(acc);
    if (lane == 0) shv[wid] = v;
    __syncthreads();
    if (threadIdx.x == 0) {
        float bsum = 0.f;
        #pragma unroll
        for (int i = 0; i < 8; i++) bsum += shv[i];
        atomicAdd(&g_var, bsum);
        __threadfence();
        unsigned int old = atomicAdd(&g_done, 1u);
        sh_last = (old == (unsigned)(GX * BB - 1));
    }
    __syncthreads();

    if (sh_last && threadIdx.x == 0) {
        __threadfence();
        float bg = 0.f;
        #pragma unroll
        for (int bb = 0; bb < BB; bb++) bg += *((volatile float*)&g_cnts[bb][0]);
        float den = (float)BB * (float)NN - 0.5f * bg;
        float seg_loss = (*((volatile float*)&g_ce)) / den;
        float var_loss = *((volatile float*)&g_var);
        // dist_loss == 0 exactly (reference adds DELTA_D before the relu),
        // reg_loss == 0.
        out[0] = seg_loss + var_loss;
    }
    __syncthreads();   // finalize reads g_cnts/g_ce before cleanup zeros them

    if (sh_last) {
        // Self-clean scratch so the next graph replay starts from zeros.
        float* ps = &g_sums[0][0][0];
        for (int i = threadIdx.x; i < BB * LL * DD; i += TPB) ps[i] = 0.f;
        float* pc = &g_cnts[0][0];
        for (int i = threadIdx.x; i < BB * LL; i += TPB) pc[i] = 0.f;
        if (threadIdx.x == 0) {
            g_ce = 0.f;
            g_var = 0.f;
            __threadfence();
            g_done = 0u;
        }
    }
}

extern "C" void kernel_launch(void* const* d_in, const int* in_sizes, int n_in,
                              void* d_out, int out_size) {
    const float* emb = (const float*)d_in[0];  // [16,4,288,800] f32
    const float* bin = (const float*)d_in[1];  // [16,2,288,800] f32
    const int*   seg = (const int*)d_in[2];    // [16,288,800] i32
    float* out = (float*)d_out;

    dim3 grid(GX, BB);
    k_pass1<<<grid, TPB>>>(emb, bin, seg);
    k_pass2<<<grid, TPB>>>(emb, seg, out);
}

// round 7
// speedup vs baseline: 1.9119x; 1.0615x over previous
#include <cuda_runtime.h>
#include <math.h>

#define BB 16
#define DD 4
#define HH 288
#define WW 800
#define NN (HH * WW)        // 230400
#define NQ (NN / 4)         // 57600 quads
#define LL 5
#define DELTA_V 0.5f
#define TPB 256
// pass1: GX1*TPB*ITERS1 = 25*256*9 = 57600 = NQ exactly (measured at roofline)
#define GX1 25
#define ITERS1 9
// pass2: GX2*TPB*ITERS2 = 45*256*5 = 57600 = NQ exactly; 720 blocks ~ 4.9/SM
#define GX2 45
#define ITERS2 5

// Scratch (allocation-free __device__ globals; zero at module load, re-zeroed
// by the last pass-2 block after each run => replays start clean).
__device__ float g_sums[BB][LL][DD] = {};
__device__ float g_cnts[BB][LL] = {};
__device__ float g_ce = 0.f;
__device__ float g_var = 0.f;
__device__ unsigned int g_done = 0u;

__device__ __forceinline__ float warp_red(float v) {
    #pragma unroll
    for (int o = 16; o > 0; o >>= 1) v += __shfl_down_sync(0xffffffffu, v, o);
    return v;
}

// L2 residency: emb/seg loaded in pass 1 with an evict_last cache-hint policy
// (valid PTX: createpolicy + .L2::cache_hint) so their 73.7MB survive in the
// ~120MB L2 for pass 2. bin is read exactly once -> ld.global.cs (streaming).
__device__ __forceinline__ unsigned long long policy_evict_last() {
    unsigned long long p;
    asm("createpolicy.fractional.L2::evict_last.b64 %0, 1.0;" : "=l"(p));
    return p;
}
__device__ __forceinline__ float4 ld_hint_f4(const float4* p,
                                             unsigned long long pol) {
    float4 v;
    asm volatile("ld.global.nc.L2::cache_hint.v4.f32 {%0,%1,%2,%3}, [%4], %5;"
        : "=f"(v.x), "=f"(v.y), "=f"(v.z), "=f"(v.w) : "l"(p), "l"(pol));
    return v;
}
__device__ __forceinline__ int4 ld_hint_i4(const int4* p,
                                           unsigned long long pol) {
    int4 v;
    asm volatile("ld.global.nc.L2::cache_hint.v4.b32 {%0,%1,%2,%3}, [%4], %5;"
        : "=r"(v.x), "=r"(v.y), "=r"(v.z), "=r"(v.w) : "l"(p), "l"(pol));
    return v;
}
__device__ __forceinline__ float4 ld_stream_f4(const float4* p) {
    float4 v;
    asm volatile("ld.global.cs.v4.f32 {%0,%1,%2,%3}, [%4];"
        : "=f"(v.x), "=f"(v.y), "=f"(v.z), "=f"(v.w) : "l"(p));
    return v;
}

__device__ __forceinline__ void px1(int lab,
                                    float a0, float a1, float a2, float a3,
                                    float x0, float x1,
                                    unsigned long long* s01,
                                    unsigned long long* s23,
                                    float* cnt, float& ce) {
    unsigned long long e01, e23;
    asm("mov.b64 %0, {%1, %2};" : "=l"(e01) : "f"(a0), "f"(a1));
    asm("mov.b64 %0, {%1, %2};" : "=l"(e23) : "f"(a2), "f"(a3));
    #pragma unroll
    for (int l = 0; l < LL; l++) {
        asm volatile("{\n\t"
            ".reg .pred p;\n\t"
            "setp.eq.s32 p, %3, %4;\n\t"
            "@p add.f32 %0, %0, 0f3F800000;\n\t"
            "@p add.rn.f32x2 %1, %1, %5;\n\t"
            "@p add.rn.f32x2 %2, %2, %6;\n\t"
            "}"
            : "+f"(cnt[l]), "+l"(s01[l]), "+l"(s23[l])
            : "r"(lab), "r"(l), "l"(e01), "l"(e23));
    }
    // weighted binary CE via softplus: nll = max(u,0) + log(1+exp(-|u|))
    float z = x1 - x0;
    bool fg = lab > 0;
    float u = fg ? -z : z;
    float eu = __expf(-fabsf(u));
    float sp = fmaxf(u, 0.f) + __logf(1.f + eu);
    ce += fg ? sp : 0.5f * sp;
}

// Pass 1: per-(batch,label) embedding sums + counts + CE numerator.
__global__ void __launch_bounds__(TPB) k_pass1(const float* __restrict__ emb,
                                               const float* __restrict__ bin,
                                               const int*   __restrict__ seg) {
    const int b = blockIdx.y;
    const float4* ep = (const float4*)(emb + (size_t)b * DD * NN);
    const float4* bp = (const float4*)(bin + (size_t)b * 2 * NN);
    const int4*   sp = (const int4*)(seg + (size_t)b * NN);
    const unsigned long long pol = policy_evict_last();

    unsigned long long s01[LL], s23[LL];
    float cnt[LL];
    #pragma unroll
    for (int l = 0; l < LL; l++) { s01[l] = 0ull; s23[l] = 0ull; cnt[l] = 0.f; }
    float ce = 0.f;

    #pragma unroll 3
    for (int it = 0; it < ITERS1; it++) {
        int q = it * (GX1 * TPB) + blockIdx.x * TPB + threadIdx.x;
        float4 e0 = ld_hint_f4(ep + q, pol);
        float4 e1 = ld_hint_f4(ep + q + NQ, pol);
        float4 e2 = ld_hint_f4(ep + q + 2 * NQ, pol);
        float4 e3 = ld_hint_f4(ep + q + 3 * NQ, pol);
        float4 c0 = ld_stream_f4(bp + q);
        float4 c1 = ld_stream_f4(bp + q + NQ);
        int4   lv = ld_hint_i4(sp + q, pol);
        px1(lv.x, e0.x, e1.x, e2.x, e3.x, c0.x, c1.x, s01, s23, cnt, ce);
        px1(lv.y, e0.y, e1.y, e2.y, e3.y, c0.y, c1.y, s01, s23, cnt, ce);
        px1(lv.z, e0.z, e1.z, e2.z, e3.z, c0.z, c1.z, s01, s23, cnt, ce);
        px1(lv.w, e0.w, e1.w, e2.w, e3.w, c0.w, c1.w, s01, s23, cnt, ce);
    }

    float vals[26];
    #pragma unroll
    for (int l = 0; l < LL; l++) {
        float lo, hi;
        asm("mov.b64 {%0, %1}, %2;" : "=f"(lo), "=f"(hi) : "l"(s01[l]));
        vals[l * 4 + 0] = lo; vals[l * 4 + 1] = hi;
        asm("mov.b64 {%0, %1}, %2;" : "=f"(lo), "=f"(hi) : "l"(s23[l]));
        vals[l * 4 + 2] = lo; vals[l * 4 + 3] = hi;
        vals[20 + l] = cnt[l];
    }
    vals[25] = ce;

    __shared__ float sh[26];
    if (threadIdx.x < 26) sh[threadIdx.x] = 0.f;
    __syncthreads();
    const int lane = threadIdx.x & 31;
    #pragma unroll
    for (int i = 0; i < 26; i++) {
        float v = warp_red(vals[i]);
        if (lane == 0) atomicAdd(&sh[i], v);
    }
    __syncthreads();
    if (threadIdx.x < 20) {
        atomicAdd(&g_sums[b][threadIdx.x >> 2][threadIdx.x & 3], sh[threadIdx.x]);
    } else if (threadIdx.x < 25) {
        atomicAdd(&g_cnts[b][threadIdx.x - 20], sh[threadIdx.x]);
    } else if (threadIdx.x == 25) {
        atomicAdd(&g_ce, sh[25]);
    }
}

// Pass 2: per-pixel hinge with pre-normalized weight LUT, fused finalization
// and scratch cleanup for the next graph replay.
__global__ void __launch_bounds__(TPB) k_pass2(const float* __restrict__ emb,
                                               const int*   __restrict__ seg,
                                               float* __restrict__ out) {
    const int b = blockIdx.y;
    __shared__ float m0[LL], m1[LL], m2[LL], m3[LL], wsh[LL];
    __shared__ bool sh_last;
    if (threadIdx.x < LL) {
        int l = threadIdx.x;
        float c = g_cnts[b][l];
        float inv = 1.f / fmaxf(c, 1.f);
        m0[l] = g_sums[b][l][0] * inv;
        m1[l] = g_sums[b][l][1] * inv;
        m2[l] = g_sums[b][l][2] * inv;
        m3[l] = g_sums[b][l][3] * inv;
        int nl = 0;
        #pragma unroll
        for (int j = 1; j < LL; j++) nl += (g_cnts[b][j] > 0.f) ? 1 : 0;
        float w = 0.f;
        if (l > 0 && c > 0.f && nl > 0)
            w = 1.f / (c * (float)nl * (float)BB);
        wsh[l] = w;
    }
    __syncthreads();

    const float4* ep = (const float4*)(emb + (size_t)b * DD * NN);
    const int4*   sp = (const int4*)(seg + (size_t)b * NN);

    float acc = 0.f;
    #pragma unroll
    for (int it = 0; it < ITERS2; it++) {
        int q = it * (GX2 * TPB) + blockIdx.x * TPB + threadIdx.x;
        float4 e0 = ep[q];
        float4 e1 = ep[q + NQ];
        float4 e2 = ep[q + 2 * NQ];
        float4 e3 = ep[q + 3 * NQ];
        int4 lv = sp[q];
        #pragma unroll
        for (int j = 0; j < 4; j++) {
            int lab = (j == 0) ? lv.x : (j == 1) ? lv.y : (j == 2) ? lv.z : lv.w;
            float a0 = (j == 0) ? e0.x : (j == 1) ? e0.y : (j == 2) ? e0.z : e0.w;
            float a1 = (j == 0) ? e1.x : (j == 1) ? e1.y : (j == 2) ? e1.z : e1.w;
            float a2 = (j == 0) ? e2.x : (j == 1) ? e2.y : (j == 2) ? e2.z : e2.w;
            float a3 = (j == 0) ? e3.x : (j == 1) ? e3.y : (j == 2) ? e3.z : e3.w;
            float d0 = a0 - m0[lab];
            float d1 = a1 - m1[lab];
            float d2 = a2 - m2[lab];
            float d3 = a3 - m3[lab];
            float sq = fmaf(d0, d0, fmaf(d1, d1, fmaf(d2, d2, d3 * d3)));
            float dist = sqrtf(sq);
            float h = fmaxf(dist - DELTA_V, 0.f);
            acc = fmaf(wsh[lab], h * h, acc);
        }
    }

    __shared__ float shv[8];
    const int lane = threadIdx.x & 31;
    const int wid = threadIdx.x >> 5;
    float v = warp_red(acc);
    if (lane == 0) shv[wid] = v;
    __syncthreads();
    if (threadIdx.x == 0) {
        float bsum = 0.f;
        #pragma unroll
        for (int i = 0; i < 8; i++) bsum += shv[i];
        atomicAdd(&g_var, bsum);
        __threadfence();
        unsigned int old = atomicAdd(&g_done, 1u);
        sh_last = (old == (unsigned)(GX2 * BB - 1));
    }
    __syncthreads();

    if (sh_last && threadIdx.x == 0) {
        __threadfence();
        float bg = 0.f;
        #pragma unroll
        for (int bb = 0; bb < BB; bb++) bg += *((volatile float*)&g_cnts[bb][0]);
        float den = (float)BB * (float)NN - 0.5f * bg;
        float seg_loss = (*((volatile float*)&g_ce)) / den;
        float var_loss = *((volatile float*)&g_var);
        // dist_loss == 0 exactly (reference adds DELTA_D before the relu),
        // reg_loss == 0.
        out[0] = seg_loss + var_loss;
    }
    __syncthreads();   // finalize reads g_cnts/g_ce before cleanup zeros them

    if (sh_last) {
        float* ps = &g_sums[0][0][0];
        for (int i = threadIdx.x; i < BB * LL * DD; i += TPB) ps[i] = 0.f;
        float* pc = &g_cnts[0][0];
        for (int i = threadIdx.x; i < BB * LL; i += TPB) pc[i] = 0.f;
        if (threadIdx.x == 0) {
            g_ce = 0.f;
            g_var = 0.f;
            __threadfence();
            g_done = 0u;
        }
    }
}

extern "C" void kernel_launch(void* const* d_in, const int* in_sizes, int n_in,
                              void* d_out, int out_size) {
    const float* emb = (const float*)d_in[0];  // [16,4,288,800] f32
    const float* bin = (const float*)d_in[1];  // [16,2,288,800] f32
    const int*   seg = (const int*)d_in[2];    // [16,288,800] i32
    float* out = (float*)d_out;

    k_pass1<<<dim3(GX1, BB), TPB>>>(emb, bin, seg);
    k_pass2<<<dim3(GX2, BB), TPB>>>(emb, seg, out);
}